// round 15
// baseline (speedup 1.0000x reference)
#include <cuda_runtime.h>
#include <math.h>
#include <stdint.h>

// ---------------------------------------------------------------------------
// Problem constants
// ---------------------------------------------------------------------------
namespace {
constexpr int B_  = 2;
constexpr int N_  = 512;
constexpr int D_  = 128;
constexpr int PH_ = 64;
constexpr int AH_ = 512;
constexpr int K_  = 16;
constexpr int M1  = B_ * N_;    // 1024
constexpr int M2  = M1 * K_;    // 16384
constexpr int NC_ = AH_ + D_;   // 640
constexpr int QKW = 2 * AH_ + D_;   // 1152: [QA(512) | KA(512) | V(128)] per query row
}

// ---------------------------------------------------------------------------
// Scratch
// ---------------------------------------------------------------------------
__device__ int   g_idx[M1 * K_];
__device__ float g_hid[M2 * PH_];
__device__ float g_QK [M1 * QKW];       // per query row: QA | KA | V
__device__ float g_Wqa[2 * D_ * AH_];   // rows 0..127 = wqkv_q@aw1, 128..255 = wqkv_k@aw1
__device__ float g_Wc [PH_ * NC_];      // [pw2@aw1 | pw2]
__device__ float g_bc [NC_];            // [pb2@aw1 + ab1 | pb2]

__device__ __forceinline__ uint32_t f2tf32(float f) {
    uint32_t u;
    asm("cvt.rna.tf32.f32 %0, %1;" : "=r"(u) : "f"(f));
    return u;
}

__device__ __forceinline__ void mma_tf32(float c[4],
                                         uint32_t a0, uint32_t a1, uint32_t a2, uint32_t a3,
                                         uint32_t b0, uint32_t b1) {
    asm volatile(
        "mma.sync.aligned.m16n8k8.row.col.f32.tf32.tf32.f32 "
        "{%0,%1,%2,%3}, {%4,%5,%6,%7}, {%8,%9}, {%0,%1,%2,%3};"
        : "+f"(c[0]), "+f"(c[1]), "+f"(c[2]), "+f"(c[3])
        : "r"(a0), "r"(a1), "r"(a2), "r"(a3), "r"(b0), "r"(b1));
}

// ---------------------------------------------------------------------------
// 1) knn+hid (blocks 0..127: 8 queries each, all 8 warps do KNN) +
//    prep_w (blocks 128..674: proven R8 4-way split-K)
// ---------------------------------------------------------------------------
__global__ __launch_bounds__(256)
void knnhid_prep_kernel(const float* __restrict__ pos,
                        const float* __restrict__ pw1, const float* __restrict__ pb1,
                        const float* __restrict__ pw2, const float* __restrict__ pb2,
                        const float* __restrict__ aw1, const float* __restrict__ ab1) {
    const int blk = blockIdx.x;
    const int tid = threadIdx.x;

    if (blk >= 128) {
        // ---------------- prep_w (proven R8) ----------------
        const int b2 = blk - 128;
        if (b2 < 512) {
            __shared__ float red[4][64];
            const int o = b2 * 64 + (tid & 63);
            const int h = o >> 9, c = o & (AH_ - 1);
            const int sp = tid >> 6;
            float s = 0.f;
#pragma unroll
            for (int u = 0; u < 32; ++u) {
                const int d = sp * 32 + u;
                s = fmaf(pw2[h * D_ + d], aw1[d * AH_ + c], s);
            }
            red[sp][tid & 63] = s;
            __syncthreads();
            if (tid < 64)
                g_Wc[h * NC_ + c] = red[0][tid] + red[1][tid] + red[2][tid] + red[3][tid];
        } else if (b2 < 544) {
            const int u = (b2 - 512) * 256 + tid;
            const int h = u >> 7, d = u & (D_ - 1);
            g_Wc[h * NC_ + AH_ + d] = pw2[h * D_ + d];
        } else {
            const int c = (b2 - 544) * 256 + tid;
            if (c < AH_) {
                float s0 = ab1[c], s1 = 0.f;
#pragma unroll 16
                for (int d = 0; d < D_; d += 2) {
                    s0 = fmaf(pb2[d],     aw1[d * AH_ + c],       s0);
                    s1 = fmaf(pb2[d + 1], aw1[(d + 1) * AH_ + c], s1);
                }
                g_bc[c] = s0 + s1;
            } else if (c < NC_) {
                g_bc[c] = pb2[c - AH_];
            }
        }
        return;
    }

    // ---------------- knn + hid ----------------
    __shared__ float spx[N_], spy[N_], spz[N_];
    __shared__ int   s_idx[8][K_];

    const int m0 = blk * 8;          // 8 queries per block, same batch (512 % 8 == 0)
    const int b = m0 >> 9;
    const int lane = tid & 31;
    const int warp = tid >> 5;

    for (int t = tid; t < N_; t += 256) {
        const float* p = pos + (size_t)(b * N_ + t) * 3;
        spx[t] = p[0]; spy[t] = p[1]; spz[t] = p[2];
    }
    __syncthreads();

    {   // ---- KNN: one warp per query (exact R3 arithmetic) ----
        const int m = m0 + warp;
        const int i = m & (N_ - 1);
        const float px = spx[i], py = spy[i], pz = spz[i];
        float d2[16];
#pragma unroll
        for (int t = 0; t < 16; ++t) {
            const int j = lane + 32 * t;
            const float dx = px - spx[j], dy = py - spy[j], dz = pz - spz[j];
            d2[t] = dx * dx + dy * dy + dz * dz;
        }
        unsigned taken = 0u;
        for (int it = 0; it < K_; ++it) {
            float best = 3.4e38f;
            int bt = -1;
#pragma unroll
            for (int t = 0; t < 16; ++t) {
                if (!((taken >> t) & 1u) && d2[t] < best) { best = d2[t]; bt = t; }
            }
            int bj = (bt < 0) ? 0x7fffffff : (lane + 32 * bt);
#pragma unroll
            for (int off = 16; off; off >>= 1) {
                const float ov = __shfl_xor_sync(0xffffffffu, best, off);
                const int   oj = __shfl_xor_sync(0xffffffffu, bj,   off);
                if (ov < best || (ov == best && oj < bj)) { best = ov; bj = oj; }
            }
            if ((bj & 31) == lane) taken |= 1u << (bj >> 5);
            if (lane == 0) { s_idx[warp][it] = bj; g_idx[m * K_ + it] = bj; }
        }
    }
    __syncthreads();

    // ---- hid for 8 queries x 16 neighbors: 4 groups of 64 threads ----
    const int h = tid & 63;
    const int grp = tid >> 6;
    const float w0 = pw1[h], w1 = pw1[64 + h], w2 = pw1[128 + h], bb = pb1[h];
#pragma unroll
    for (int r = grp * 32; r < grp * 32 + 32; ++r) {
        const int q = r >> 4, kk = r & 15;
        const int iq = (m0 + q) & (N_ - 1);
        const int j = s_idx[q][kk];
        const float rx = spx[iq] - spx[j];
        const float ry = spy[iq] - spy[j];
        const float rz = spz[iq] - spz[j];
        float v = fmaf(rx, w0, fmaf(ry, w1, fmaf(rz, w2, bb)));
        g_hid[(size_t)(m0 * K_ + r) * PH_ + h] = fmaxf(v, 0.f);
    }
}

// ---------------------------------------------------------------------------
// 2) wqa_gemm: g_Wqa rows 0..127 = wqkv[:, 0:128]@aw1, rows 128..255 = wqkv[:,128:256]@aw1
//    (proven double-buffered skeleton; A rows read from wqkv with stride 384)
// ---------------------------------------------------------------------------
__global__ __launch_bounds__(256)
void wqa_gemm(const float* __restrict__ wqkv, const float* __restrict__ aw1) {
    __shared__ uint32_t As[2][128][36];
    __shared__ uint32_t Bs[2][32][136];

    const int tid  = threadIdx.x;
    const int lane = tid & 31;
    const int warp = tid >> 5;
    const int wm = (warp >> 2) * 64;
    const int wn = (warp & 3) * 32;
    const int m0 = blockIdx.y * 128;          // 0 or 128
    const int n0 = blockIdx.x * 128;
    const int koff = (m0 >= 128) ? 128 : 0;   // q-half vs k-half of wqkv

    float acc[4][4][4];
#pragma unroll
    for (int mi = 0; mi < 4; ++mi)
#pragma unroll
        for (int ni = 0; ni < 4; ++ni)
#pragma unroll
            for (int e = 0; e < 4; ++e) acc[mi][ni][e] = 0.f;

    auto stage = [&](int k0, int buf) {
#pragma unroll
        for (int t = 0; t < 4; ++t) {
            const int idx = tid + t * 256;
            const int r = idx >> 3, c = (idx & 7) << 2;
            const float4 v = *(const float4*)(wqkv + (size_t)r * 384 + koff + k0 + c);
            As[buf][r][c + 0] = f2tf32(v.x); As[buf][r][c + 1] = f2tf32(v.y);
            As[buf][r][c + 2] = f2tf32(v.z); As[buf][r][c + 3] = f2tf32(v.w);
        }
#pragma unroll
        for (int t = 0; t < 4; ++t) {
            const int idx = tid + t * 256;
            const int kr = idx >> 5, nc = (idx & 31) << 2;
            const float4 v = *(const float4*)(aw1 + (size_t)(k0 + kr) * AH_ + n0 + nc);
            Bs[buf][kr][nc + 0] = f2tf32(v.x); Bs[buf][kr][nc + 1] = f2tf32(v.y);
            Bs[buf][kr][nc + 2] = f2tf32(v.z); Bs[buf][kr][nc + 3] = f2tf32(v.w);
        }
    };

    auto mmatile = [&](int buf) {
#pragma unroll
        for (int ks = 0; ks < 4; ++ks) {
            const int kk = ks * 8;
            uint32_t af[4][4], bf[4][2];
#pragma unroll
            for (int mi = 0; mi < 4; ++mi) {
                const int rb = wm + mi * 16 + (lane >> 2);
                const int cb = kk + (lane & 3);
                af[mi][0] = As[buf][rb    ][cb    ];
                af[mi][1] = As[buf][rb + 8][cb    ];
                af[mi][2] = As[buf][rb    ][cb + 4];
                af[mi][3] = As[buf][rb + 8][cb + 4];
            }
#pragma unroll
            for (int ni = 0; ni < 4; ++ni) {
                const int nb = wn + ni * 8 + (lane >> 2);
                bf[ni][0] = Bs[buf][kk +     (lane & 3)][nb];
                bf[ni][1] = Bs[buf][kk + 4 + (lane & 3)][nb];
            }
#pragma unroll
            for (int mi = 0; mi < 4; ++mi)
#pragma unroll
                for (int ni = 0; ni < 4; ++ni)
                    mma_tf32(acc[mi][ni], af[mi][0], af[mi][1], af[mi][2], af[mi][3],
                             bf[ni][0], bf[ni][1]);
        }
    };

    stage(0, 0);
    __syncthreads();
#pragma unroll
    for (int t = 0; t < 4; ++t) {
        if (t < 3) stage((t + 1) << 5, (t + 1) & 1);
        mmatile(t & 1);
        __syncthreads();
    }

#pragma unroll
    for (int mi = 0; mi < 4; ++mi) {
        const int r0 = m0 + wm + mi * 16 + (lane >> 2);
#pragma unroll
        for (int ni = 0; ni < 4; ++ni) {
            const int c0 = n0 + wn + ni * 8 + ((lane & 3) << 1);
            *(float2*)(g_Wqa + (size_t)r0 * AH_ + c0)       = make_float2(acc[mi][ni][0], acc[mi][ni][1]);
            *(float2*)(g_Wqa + (size_t)(r0 + 8) * AH_ + c0) = make_float2(acc[mi][ni][2], acc[mi][ni][3]);
        }
    }
}

// ---------------------------------------------------------------------------
// 3) xqk_gemm: [QA | KA | V] = x^T @ [Wqa | Wka | wqkv_v]
//    M=1024, N=1152, K=128. A read transposed straight from x (coalesced along n).
// ---------------------------------------------------------------------------
__global__ __launch_bounds__(256)
void xqk_gemm(const float* __restrict__ x, const float* __restrict__ wqkv) {
    __shared__ uint32_t As[2][128][36];
    __shared__ uint32_t Bs[2][32][136];

    const int tid  = threadIdx.x;
    const int lane = tid & 31;
    const int warp = tid >> 5;
    const int wm = (warp >> 2) * 64;
    const int wn = (warp & 3) * 32;
    const int m0 = blockIdx.y * 128;
    const int n0 = blockIdx.x * 128;   // 0..1024
    const size_t xb  = (size_t)(m0 >> 9) * (D_ * N_);
    const int   nlow = m0 & (N_ - 1);

    float acc[4][4][4];
#pragma unroll
    for (int mi = 0; mi < 4; ++mi)
#pragma unroll
        for (int ni = 0; ni < 4; ++ni)
#pragma unroll
            for (int e = 0; e < 4; ++e) acc[mi][ni][e] = 0.f;

    auto stage = [&](int k0, int buf) {
#pragma unroll
        for (int t = 0; t < 4; ++t) {
            const int idx = tid + t * 256;
            const int r0 = (idx & 31) << 2, c = idx >> 5;   // vec along m (n of x)
            const float4 v = *(const float4*)(x + xb + (size_t)(k0 + c) * N_ + nlow + r0);
            As[buf][r0 + 0][c] = f2tf32(v.x);
            As[buf][r0 + 1][c] = f2tf32(v.y);
            As[buf][r0 + 2][c] = f2tf32(v.z);
            As[buf][r0 + 3][c] = f2tf32(v.w);
        }
#pragma unroll
        for (int t = 0; t < 4; ++t) {
            const int idx = tid + t * 256;
            const int kr = idx >> 5, nc = (idx & 31) << 2;
            const float* src;
            if (n0 < AH_)            src = g_Wqa + (size_t)(k0 + kr) * AH_ + n0 + nc;
            else if (n0 < 2 * AH_)   src = g_Wqa + (size_t)(D_ + k0 + kr) * AH_ + (n0 - AH_) + nc;
            else                     src = wqkv + (size_t)(k0 + kr) * 384 + 256 + nc;
            const float4 v = *(const float4*)src;
            Bs[buf][kr][nc + 0] = f2tf32(v.x); Bs[buf][kr][nc + 1] = f2tf32(v.y);
            Bs[buf][kr][nc + 2] = f2tf32(v.z); Bs[buf][kr][nc + 3] = f2tf32(v.w);
        }
    };

    auto mmatile = [&](int buf) {
#pragma unroll
        for (int ks = 0; ks < 4; ++ks) {
            const int kk = ks * 8;
            uint32_t af[4][4], bf[4][2];
#pragma unroll
            for (int mi = 0; mi < 4; ++mi) {
                const int rb = wm + mi * 16 + (lane >> 2);
                const int cb = kk + (lane & 3);
                af[mi][0] = As[buf][rb    ][cb    ];
                af[mi][1] = As[buf][rb + 8][cb    ];
                af[mi][2] = As[buf][rb    ][cb + 4];
                af[mi][3] = As[buf][rb + 8][cb + 4];
            }
#pragma unroll
            for (int ni = 0; ni < 4; ++ni) {
                const int nb = wn + ni * 8 + (lane >> 2);
                bf[ni][0] = Bs[buf][kk +     (lane & 3)][nb];
                bf[ni][1] = Bs[buf][kk + 4 + (lane & 3)][nb];
            }
#pragma unroll
            for (int mi = 0; mi < 4; ++mi)
#pragma unroll
                for (int ni = 0; ni < 4; ++ni)
                    mma_tf32(acc[mi][ni], af[mi][0], af[mi][1], af[mi][2], af[mi][3],
                             bf[ni][0], bf[ni][1]);
        }
    };

    stage(0, 0);
    __syncthreads();
#pragma unroll
    for (int t = 0; t < 4; ++t) {
        if (t < 3) stage((t + 1) << 5, (t + 1) & 1);
        mmatile(t & 1);
        __syncthreads();
    }

#pragma unroll
    for (int mi = 0; mi < 4; ++mi) {
        const int r0 = m0 + wm + mi * 16 + (lane >> 2);
#pragma unroll
        for (int ni = 0; ni < 4; ++ni) {
            const int c0 = n0 + wn + ni * 8 + ((lane & 3) << 1);
            *(float2*)(g_QK + (size_t)r0 * QKW + c0)       = make_float2(acc[mi][ni][0], acc[mi][ni][1]);
            *(float2*)(g_QK + (size_t)(r0 + 8) * QKW + c0) = make_float2(acc[mi][ni][2], acc[mi][ni][3]);
        }
    }
}

// ---------------------------------------------------------------------------
// 4) MEGA-FUSED (proven R14 pipelined version; only g_QK addressing updated)
// ---------------------------------------------------------------------------
constexpr int SM_HID = 0;
constexpr int SM_BS  = 17408;
constexpr int SM_ASA = 34816;
constexpr int SM_SIM = 68608;
constexpr int SM_QA  = 102400;
constexpr int SM_JJ  = 104512;
constexpr int SM_TOT = 104768;

__global__ __launch_bounds__(256, 2)
void fused_kernel(const float* __restrict__ aw2, float* __restrict__ out) {
    extern __shared__ char smem[];
    uint32_t* sHid = (uint32_t*)(smem + SM_HID);
    uint32_t* sAsA = (uint32_t*)(smem + SM_ASA);
    float*    sPE  = (float*)   (smem + SM_ASA);
    float*    sSIM = (float*)   (smem + SM_SIM);
    float*    sQA  = (float*)   (smem + SM_QA);
    int*      sJJ  = (int*)     (smem + SM_JJ);
    uint32_t* sBuf0 = (uint32_t*)(smem + SM_BS);
    uint32_t* sBuf1 = (uint32_t*)(smem + SM_SIM);   // aliases sSIM until final dump

    const int tid  = threadIdx.x;
    const int lane = tid & 31;
    const int warp = tid >> 5;
    const int wm = (warp >> 2) * 32;
    const int wn = (warp & 3) * 32;
    const int m0 = blockIdx.x * 64;
    const int b  = m0 >> 13;
    const int q0 = m0 >> 4;

    // ---- stage hid (64x64 tf32), neighbor indices, sQA(ch=0), tile0 ----
#pragma unroll
    for (int t = 0; t < 4; ++t) {
        const int idx = tid + t * 256;
        const int r = idx >> 4, c = (idx & 15) << 2;
        const float4 v = *(const float4*)(g_hid + (size_t)(m0 + r) * PH_ + c);
        sHid[r * 68 + c + 0] = f2tf32(v.x); sHid[r * 68 + c + 1] = f2tf32(v.y);
        sHid[r * 68 + c + 2] = f2tf32(v.z); sHid[r * 68 + c + 3] = f2tf32(v.w);
    }
    if (tid < 64) sJJ[tid] = g_idx[m0 + tid];
#pragma unroll
    for (int t = 0; t < 2; ++t) {
        const int u = tid + t * 256;
        const int q = u >> 7, c = u & 127;
        sQA[q * 132 + c] = g_QK[(size_t)(q0 + q) * QKW + c];
    }
#pragma unroll
    for (int u = 0; u < 4; ++u) {   // tile 0 = Wc(ch0, t0) -> buf0
        const int idx = tid + u * 256;
        const int kr = idx >> 5, nc = (idx & 31) << 2;
        const float4 v = *(const float4*)(g_Wc + (size_t)kr * NC_ + nc);
        sBuf0[kr * 136 + nc + 0] = f2tf32(v.x); sBuf0[kr * 136 + nc + 1] = f2tf32(v.y);
        sBuf0[kr * 136 + nc + 2] = f2tf32(v.z); sBuf0[kr * 136 + nc + 3] = f2tf32(v.w);
    }
    __syncthreads();

    float accA[2][4][4], accS[2][4][4];
#pragma unroll
    for (int mi = 0; mi < 2; ++mi)
#pragma unroll
        for (int ni = 0; ni < 4; ++ni)
#pragma unroll
            for (int e = 0; e < 4; ++e) { accA[mi][ni][e] = 0.f; accS[mi][ni][e] = 0.f; }

    // ================= 26-tile pipeline =================
    for (int i = 0; i < 26; ++i) {
        // ---- prefetch tile i+1 into registers ----
        float4 pf[4];
        const int in = i + 1;
        int chn = 0, sn = 0;
        if (in < 26) {
            if (in < 24) { chn = in / 6; sn = in % 6; }
#pragma unroll
            for (int u = 0; u < 4; ++u) {
                const int idx = tid + u * 256;
                const int kr = idx >> 5, nc = (idx & 31) << 2;
                const float* src;
                if (in >= 24)    src = g_Wc + (size_t)(32 * (in - 24) + kr) * NC_ + AH_ + nc;
                else if (sn < 2) src = g_Wc + (size_t)(32 * sn + kr) * NC_ + chn * 128 + nc;
                else             src = aw2 + (size_t)(chn * 128 + (sn - 2) * 32 + kr) * D_ + nc;
                pf[u] = *(const float4*)src;
            }
        }

        // ---- consume tile i from buffer i&1 ----
        const uint32_t* Bs = (i & 1) ? sBuf1 : sBuf0;
        if (i < 24) {
            const int ch = i / 6, s = i % 6;
            if (s < 2) {
                // Ablk += hid @ Wc-tile
#pragma unroll
                for (int ks = 0; ks < 4; ++ks) {
                    const int kk = ks * 8;
                    uint32_t af[2][4], bf[4][2];
#pragma unroll
                    for (int mi = 0; mi < 2; ++mi) {
                        const int rb = wm + mi * 16 + (lane >> 2);
                        const int cb = 32 * s + kk + (lane & 3);
                        af[mi][0] = sHid[rb * 68 + cb];
                        af[mi][1] = sHid[(rb + 8) * 68 + cb];
                        af[mi][2] = sHid[rb * 68 + cb + 4];
                        af[mi][3] = sHid[(rb + 8) * 68 + cb + 4];
                    }
#pragma unroll
                    for (int ni = 0; ni < 4; ++ni) {
                        const int nb = wn + ni * 8 + (lane >> 2);
                        bf[ni][0] = Bs[(kk +     (lane & 3)) * 136 + nb];
                        bf[ni][1] = Bs[(kk + 4 + (lane & 3)) * 136 + nb];
                    }
#pragma unroll
                    for (int mi = 0; mi < 2; ++mi)
#pragma unroll
                        for (int ni = 0; ni < 4; ++ni)
                            mma_tf32(accA[mi][ni], af[mi][0], af[mi][1], af[mi][2], af[mi][3],
                                     bf[ni][0], bf[ni][1]);
                }
                if (s == 1) {
                    // epilogue: + bc + QA - KA, relu -> sAsA (tf32); reset accA
#pragma unroll
                    for (int mi = 0; mi < 2; ++mi) {
                        const int lr = wm + mi * 16 + (lane >> 2);
                        const int q  = lr >> 4;
                        const int j0 = sJJ[lr], j1 = sJJ[lr + 8];
                        const size_t ka0b = (size_t)(b * N_ + j0) * QKW + AH_ + ch * 128;
                        const size_t ka1b = (size_t)(b * N_ + j1) * QKW + AH_ + ch * 128;
#pragma unroll
                        for (int ni = 0; ni < 4; ++ni) {
                            const int cl = wn + ni * 8 + ((lane & 3) << 1);
                            const float bc0 = g_bc[ch * 128 + cl], bc1 = g_bc[ch * 128 + cl + 1];
                            const float qa0 = sQA[q * 132 + cl], qa1 = sQA[q * 132 + cl + 1];
                            const float2 ka0 = *(const float2*)(g_QK + ka0b + cl);
                            const float2 ka1 = *(const float2*)(g_QK + ka1b + cl);
                            const float x0 = fmaxf(accA[mi][ni][0] + bc0 + qa0 - ka0.x, 0.f);
                            const float x1 = fmaxf(accA[mi][ni][1] + bc1 + qa1 - ka0.y, 0.f);
                            const float x2 = fmaxf(accA[mi][ni][2] + bc0 + qa0 - ka1.x, 0.f);
                            const float x3 = fmaxf(accA[mi][ni][3] + bc1 + qa1 - ka1.y, 0.f);
                            sAsA[lr * 132 + cl]           = f2tf32(x0);
                            sAsA[lr * 132 + cl + 1]       = f2tf32(x1);
                            sAsA[(lr + 8) * 132 + cl]     = f2tf32(x2);
                            sAsA[(lr + 8) * 132 + cl + 1] = f2tf32(x3);
                            accA[mi][ni][0] = 0.f; accA[mi][ni][1] = 0.f;
                            accA[mi][ni][2] = 0.f; accA[mi][ni][3] = 0.f;
                        }
                    }
                }
            } else {
                // SIM += Ablk @ aw2-tile
                const int ts = s - 2;
#pragma unroll
                for (int ks = 0; ks < 4; ++ks) {
                    const int kk = ks * 8;
                    uint32_t af[2][4], bf[4][2];
#pragma unroll
                    for (int mi = 0; mi < 2; ++mi) {
                        const int rb = wm + mi * 16 + (lane >> 2);
                        const int cb = ts * 32 + kk + (lane & 3);
                        af[mi][0] = sAsA[rb * 132 + cb];
                        af[mi][1] = sAsA[(rb + 8) * 132 + cb];
                        af[mi][2] = sAsA[rb * 132 + cb + 4];
                        af[mi][3] = sAsA[(rb + 8) * 132 + cb + 4];
                    }
#pragma unroll
                    for (int ni = 0; ni < 4; ++ni) {
                        const int nb = wn + ni * 8 + (lane >> 2);
                        bf[ni][0] = Bs[(kk +     (lane & 3)) * 136 + nb];
                        bf[ni][1] = Bs[(kk + 4 + (lane & 3)) * 136 + nb];
                    }
#pragma unroll
                    for (int mi = 0; mi < 2; ++mi)
#pragma unroll
                        for (int ni = 0; ni < 4; ++ni)
                            mma_tf32(accS[mi][ni], af[mi][0], af[mi][1], af[mi][2], af[mi][3],
                                     bf[ni][0], bf[ni][1]);
                }
            }
        } else {
            // PE += hid @ WcPE-tile (accumulates into recycled accA)
            const int t = i - 24;
#pragma unroll
            for (int ks = 0; ks < 4; ++ks) {
                const int kk = ks * 8;
                uint32_t af[2][4], bf[4][2];
#pragma unroll
                for (int mi = 0; mi < 2; ++mi) {
                    const int rb = wm + mi * 16 + (lane >> 2);
                    const int cb = 32 * t + kk + (lane & 3);
                    af[mi][0] = sHid[rb * 68 + cb];
                    af[mi][1] = sHid[(rb + 8) * 68 + cb];
                    af[mi][2] = sHid[rb * 68 + cb + 4];
                    af[mi][3] = sHid[(rb + 8) * 68 + cb + 4];
                }
#pragma unroll
                for (int ni = 0; ni < 4; ++ni) {
                    const int nb = wn + ni * 8 + (lane >> 2);
                    bf[ni][0] = Bs[(kk +     (lane & 3)) * 136 + nb];
                    bf[ni][1] = Bs[(kk + 4 + (lane & 3)) * 136 + nb];
                }
#pragma unroll
                for (int mi = 0; mi < 2; ++mi)
#pragma unroll
                    for (int ni = 0; ni < 4; ++ni)
                        mma_tf32(accA[mi][ni], af[mi][0], af[mi][1], af[mi][2], af[mi][3],
                                 bf[ni][0], bf[ni][1]);
            }
        }

        // ---- store prefetched tile into the other buffer ----
        if (in < 26) {
            uint32_t* Bw = (in & 1) ? sBuf1 : sBuf0;
#pragma unroll
            for (int u = 0; u < 4; ++u) {
                const int idx = tid + u * 256;
                const int kr = idx >> 5, nc = (idx & 31) << 2;
                Bw[kr * 136 + nc + 0] = f2tf32(pf[u].x);
                Bw[kr * 136 + nc + 1] = f2tf32(pf[u].y);
                Bw[kr * 136 + nc + 2] = f2tf32(pf[u].z);
                Bw[kr * 136 + nc + 3] = f2tf32(pf[u].w);
            }
            if (in < 24 && sn == 0 && chn > 0) {
#pragma unroll
                for (int t2 = 0; t2 < 2; ++t2) {
                    const int u2 = tid + t2 * 256;
                    const int q = u2 >> 7, c = u2 & 127;
                    sQA[q * 132 + c] = g_QK[(size_t)(q0 + q) * QKW + chn * 128 + c];
                }
            }
        }
        __syncthreads();
    }

    // ---- dump SIM + PE (ab2 omitted: constant over softmax axis) ----
#pragma unroll
    for (int mi = 0; mi < 2; ++mi) {
        const int lr = wm + mi * 16 + (lane >> 2);
#pragma unroll
        for (int ni = 0; ni < 4; ++ni) {
            const int cl = wn + ni * 8 + ((lane & 3) << 1);
            sSIM[lr * 132 + cl]           = accS[mi][ni][0];
            sSIM[lr * 132 + cl + 1]       = accS[mi][ni][1];
            sSIM[(lr + 8) * 132 + cl]     = accS[mi][ni][2];
            sSIM[(lr + 8) * 132 + cl + 1] = accS[mi][ni][3];
            sPE[lr * 132 + cl]           = accA[mi][ni][0] + g_bc[AH_ + cl];
            sPE[lr * 132 + cl + 1]       = accA[mi][ni][1] + g_bc[AH_ + cl + 1];
            sPE[(lr + 8) * 132 + cl]     = accA[mi][ni][2] + g_bc[AH_ + cl];
            sPE[(lr + 8) * 132 + cl + 1] = accA[mi][ni][3] + g_bc[AH_ + cl + 1];
        }
    }
    __syncthreads();

    // ---- finalize: softmax over 16 neighbors + v gather, transposed store ----
#pragma unroll
    for (int u = 0; u < 2; ++u) {
        const int item = tid + u * 256;        // 512 = 4 queries x 128 ch
        const int q = item >> 7, c = item & 127;
        const int r0 = q * 16;
        float mx = -3.4e38f;
#pragma unroll
        for (int kk = 0; kk < K_; ++kk) mx = fmaxf(mx, sSIM[(r0 + kk) * 132 + c]);
        float s = 0.f, agg = 0.f;
#pragma unroll
        for (int kk = 0; kk < K_; ++kk) {
            const float e = expf(sSIM[(r0 + kk) * 132 + c] - mx);
            s += e;
            const int j = sJJ[r0 + kk];
            const float vg = g_QK[(size_t)(b * N_ + j) * QKW + 2 * AH_ + c] + sPE[(r0 + kk) * 132 + c];
            agg = fmaf(e, vg, agg);
        }
        const int ig = (q0 + q) & (N_ - 1);
        out[(size_t)b * D_ * N_ + (size_t)c * N_ + ig] = agg / s;
    }
}

// ---------------------------------------------------------------------------
// Launch
// ---------------------------------------------------------------------------
extern "C" void kernel_launch(void* const* d_in, const int* in_sizes, int n_in,
                              void* d_out, int out_size) {
    const float* x    = (const float*)d_in[0];
    const float* pos  = (const float*)d_in[1];
    const float* wqkv = (const float*)d_in[2];
    const float* pw1  = (const float*)d_in[3];
    const float* pb1  = (const float*)d_in[4];
    const float* pw2  = (const float*)d_in[5];
    const float* pb2  = (const float*)d_in[6];
    const float* aw1  = (const float*)d_in[7];
    const float* ab1  = (const float*)d_in[8];
    const float* aw2  = (const float*)d_in[9];
    float* out = (float*)d_out;

    static bool attr_set = false;
    if (!attr_set) {
        cudaFuncSetAttribute(fused_kernel, cudaFuncAttributeMaxDynamicSharedMemorySize, SM_TOT);
        attr_set = true;
    }

    knnhid_prep_kernel<<<128 + 547, 256>>>(pos, pw1, pb1, pw2, pb2, aw1, ab1);
    wqa_gemm<<<dim3(AH_ / 128, 2), 256>>>(wqkv, aw1);
    xqk_gemm<<<dim3(QKW / 128, M1 / 128), 256>>>(x, wqkv);
    fused_kernel<<<M2 / 64, 256, SM_TOT>>>(aw2, out);
}

// round 16
// speedup vs baseline: 1.0120x; 1.0120x over previous
#include <cuda_runtime.h>
#include <math.h>
#include <stdint.h>

// ---------------------------------------------------------------------------
// Problem constants
// ---------------------------------------------------------------------------
namespace {
constexpr int B_  = 2;
constexpr int N_  = 512;
constexpr int D_  = 128;
constexpr int PH_ = 64;
constexpr int AH_ = 512;
constexpr int K_  = 16;
constexpr int M1  = B_ * N_;    // 1024
constexpr int M2  = M1 * K_;    // 16384
constexpr int NC_ = AH_ + D_;   // 640
constexpr int NX  = 2 * AH_ + D_;   // 1152 cols of the xqk gemm
}

// ---------------------------------------------------------------------------
// Scratch (dense per-quantity arrays: fused's gather geometry is R14-proven)
// ---------------------------------------------------------------------------
__device__ int   g_idx[M1 * K_];
__device__ float g_hid[M2 * PH_];
__device__ float g_QA [M1 * AH_];
__device__ float g_KA [M1 * AH_];
__device__ float g_V  [M1 * D_];
__device__ float g_Wqa[2 * D_ * AH_];   // rows 0..127 = wqkv_q@aw1, 128..255 = wqkv_k@aw1
__device__ float g_Wc [PH_ * NC_];      // [pw2@aw1 | pw2]
__device__ float g_bc [NC_];            // [pb2@aw1 + ab1 | pb2]

__device__ __forceinline__ uint32_t f2tf32(float f) {
    uint32_t u;
    asm("cvt.rna.tf32.f32 %0, %1;" : "=r"(u) : "f"(f));
    return u;
}

__device__ __forceinline__ void mma_tf32(float c[4],
                                         uint32_t a0, uint32_t a1, uint32_t a2, uint32_t a3,
                                         uint32_t b0, uint32_t b1) {
    asm volatile(
        "mma.sync.aligned.m16n8k8.row.col.f32.tf32.tf32.f32 "
        "{%0,%1,%2,%3}, {%4,%5,%6,%7}, {%8,%9}, {%0,%1,%2,%3};"
        : "+f"(c[0]), "+f"(c[1]), "+f"(c[2]), "+f"(c[3])
        : "r"(a0), "r"(a1), "r"(a2), "r"(a3), "r"(b0), "r"(b1));
}

// ---------------------------------------------------------------------------
// 1) knn+hid (blocks 0..127) + prep_w (blocks 128..674)   [proven R15]
// ---------------------------------------------------------------------------
__global__ __launch_bounds__(256)
void knnhid_prep_kernel(const float* __restrict__ pos,
                        const float* __restrict__ pw1, const float* __restrict__ pb1,
                        const float* __restrict__ pw2, const float* __restrict__ pb2,
                        const float* __restrict__ aw1, const float* __restrict__ ab1) {
    const int blk = blockIdx.x;
    const int tid = threadIdx.x;

    if (blk >= 128) {
        const int b2 = blk - 128;
        if (b2 < 512) {
            __shared__ float red[4][64];
            const int o = b2 * 64 + (tid & 63);
            const int h = o >> 9, c = o & (AH_ - 1);
            const int sp = tid >> 6;
            float s = 0.f;
#pragma unroll
            for (int u = 0; u < 32; ++u) {
                const int d = sp * 32 + u;
                s = fmaf(pw2[h * D_ + d], aw1[d * AH_ + c], s);
            }
            red[sp][tid & 63] = s;
            __syncthreads();
            if (tid < 64)
                g_Wc[h * NC_ + c] = red[0][tid] + red[1][tid] + red[2][tid] + red[3][tid];
        } else if (b2 < 544) {
            const int u = (b2 - 512) * 256 + tid;
            const int h = u >> 7, d = u & (D_ - 1);
            g_Wc[h * NC_ + AH_ + d] = pw2[h * D_ + d];
        } else {
            const int c = (b2 - 544) * 256 + tid;
            if (c < AH_) {
                float s0 = ab1[c], s1 = 0.f;
#pragma unroll 16
                for (int d = 0; d < D_; d += 2) {
                    s0 = fmaf(pb2[d],     aw1[d * AH_ + c],       s0);
                    s1 = fmaf(pb2[d + 1], aw1[(d + 1) * AH_ + c], s1);
                }
                g_bc[c] = s0 + s1;
            } else if (c < NC_) {
                g_bc[c] = pb2[c - AH_];
            }
        }
        return;
    }

    __shared__ float spx[N_], spy[N_], spz[N_];
    __shared__ int   s_idx[8][K_];

    const int m0 = blk * 8;
    const int b = m0 >> 9;
    const int lane = tid & 31;
    const int warp = tid >> 5;

    for (int t = tid; t < N_; t += 256) {
        const float* p = pos + (size_t)(b * N_ + t) * 3;
        spx[t] = p[0]; spy[t] = p[1]; spz[t] = p[2];
    }
    __syncthreads();

    {
        const int m = m0 + warp;
        const int i = m & (N_ - 1);
        const float px = spx[i], py = spy[i], pz = spz[i];
        float d2[16];
#pragma unroll
        for (int t = 0; t < 16; ++t) {
            const int j = lane + 32 * t;
            const float dx = px - spx[j], dy = py - spy[j], dz = pz - spz[j];
            d2[t] = dx * dx + dy * dy + dz * dz;
        }
        unsigned taken = 0u;
        for (int it = 0; it < K_; ++it) {
            float best = 3.4e38f;
            int bt = -1;
#pragma unroll
            for (int t = 0; t < 16; ++t) {
                if (!((taken >> t) & 1u) && d2[t] < best) { best = d2[t]; bt = t; }
            }
            int bj = (bt < 0) ? 0x7fffffff : (lane + 32 * bt);
#pragma unroll
            for (int off = 16; off; off >>= 1) {
                const float ov = __shfl_xor_sync(0xffffffffu, best, off);
                const int   oj = __shfl_xor_sync(0xffffffffu, bj,   off);
                if (ov < best || (ov == best && oj < bj)) { best = ov; bj = oj; }
            }
            if ((bj & 31) == lane) taken |= 1u << (bj >> 5);
            if (lane == 0) { s_idx[warp][it] = bj; g_idx[m * K_ + it] = bj; }
        }
    }
    __syncthreads();

    const int h = tid & 63;
    const int grp = tid >> 6;
    const float w0 = pw1[h], w1 = pw1[64 + h], w2 = pw1[128 + h], bb = pb1[h];
#pragma unroll
    for (int r = grp * 32; r < grp * 32 + 32; ++r) {
        const int q = r >> 4, kk = r & 15;
        const int iq = (m0 + q) & (N_ - 1);
        const int j = s_idx[q][kk];
        const float rx = spx[iq] - spx[j];
        const float ry = spy[iq] - spy[j];
        const float rz = spz[iq] - spz[j];
        float v = fmaf(rx, w0, fmaf(ry, w1, fmaf(rz, w2, bb)));
        g_hid[(size_t)(m0 * K_ + r) * PH_ + h] = fmaxf(v, 0.f);
    }
}

// ---------------------------------------------------------------------------
// 2) wqa_gemm: g_Wqa = [wqkv_q@aw1 ; wqkv_k@aw1]   [proven R15]
// ---------------------------------------------------------------------------
__global__ __launch_bounds__(256)
void wqa_gemm(const float* __restrict__ wqkv, const float* __restrict__ aw1) {
    __shared__ uint32_t As[2][128][36];
    __shared__ uint32_t Bs[2][32][136];

    const int tid  = threadIdx.x;
    const int lane = tid & 31;
    const int warp = tid >> 5;
    const int wm = (warp >> 2) * 64;
    const int wn = (warp & 3) * 32;
    const int m0 = blockIdx.y * 128;
    const int n0 = blockIdx.x * 128;
    const int koff = (m0 >= 128) ? 128 : 0;

    float acc[4][4][4];
#pragma unroll
    for (int mi = 0; mi < 4; ++mi)
#pragma unroll
        for (int ni = 0; ni < 4; ++ni)
#pragma unroll
            for (int e = 0; e < 4; ++e) acc[mi][ni][e] = 0.f;

    auto stage = [&](int k0, int buf) {
#pragma unroll
        for (int t = 0; t < 4; ++t) {
            const int idx = tid + t * 256;
            const int r = idx >> 3, c = (idx & 7) << 2;
            const float4 v = *(const float4*)(wqkv + (size_t)r * 384 + koff + k0 + c);
            As[buf][r][c + 0] = f2tf32(v.x); As[buf][r][c + 1] = f2tf32(v.y);
            As[buf][r][c + 2] = f2tf32(v.z); As[buf][r][c + 3] = f2tf32(v.w);
        }
#pragma unroll
        for (int t = 0; t < 4; ++t) {
            const int idx = tid + t * 256;
            const int kr = idx >> 5, nc = (idx & 31) << 2;
            const float4 v = *(const float4*)(aw1 + (size_t)(k0 + kr) * AH_ + n0 + nc);
            Bs[buf][kr][nc + 0] = f2tf32(v.x); Bs[buf][kr][nc + 1] = f2tf32(v.y);
            Bs[buf][kr][nc + 2] = f2tf32(v.z); Bs[buf][kr][nc + 3] = f2tf32(v.w);
        }
    };

    auto mmatile = [&](int buf) {
#pragma unroll
        for (int ks = 0; ks < 4; ++ks) {
            const int kk = ks * 8;
            uint32_t af[4][4], bf[4][2];
#pragma unroll
            for (int mi = 0; mi < 4; ++mi) {
                const int rb = wm + mi * 16 + (lane >> 2);
                const int cb = kk + (lane & 3);
                af[mi][0] = As[buf][rb    ][cb    ];
                af[mi][1] = As[buf][rb + 8][cb    ];
                af[mi][2] = As[buf][rb    ][cb + 4];
                af[mi][3] = As[buf][rb + 8][cb + 4];
            }
#pragma unroll
            for (int ni = 0; ni < 4; ++ni) {
                const int nb = wn + ni * 8 + (lane >> 2);
                bf[ni][0] = Bs[buf][kk +     (lane & 3)][nb];
                bf[ni][1] = Bs[buf][kk + 4 + (lane & 3)][nb];
            }
#pragma unroll
            for (int mi = 0; mi < 4; ++mi)
#pragma unroll
                for (int ni = 0; ni < 4; ++ni)
                    mma_tf32(acc[mi][ni], af[mi][0], af[mi][1], af[mi][2], af[mi][3],
                             bf[ni][0], bf[ni][1]);
        }
    };

    stage(0, 0);
    __syncthreads();
#pragma unroll
    for (int t = 0; t < 4; ++t) {
        if (t < 3) stage((t + 1) << 5, (t + 1) & 1);
        mmatile(t & 1);
        __syncthreads();
    }

#pragma unroll
    for (int mi = 0; mi < 4; ++mi) {
        const int r0 = m0 + wm + mi * 16 + (lane >> 2);
#pragma unroll
        for (int ni = 0; ni < 4; ++ni) {
            const int c0 = n0 + wn + ni * 8 + ((lane & 3) << 1);
            *(float2*)(g_Wqa + (size_t)r0 * AH_ + c0)       = make_float2(acc[mi][ni][0], acc[mi][ni][1]);
            *(float2*)(g_Wqa + (size_t)(r0 + 8) * AH_ + c0) = make_float2(acc[mi][ni][2], acc[mi][ni][3]);
        }
    }
}

// ---------------------------------------------------------------------------
// 3) xqk_gemm: [QA | KA | V] = x^T @ [Wqa | Wka | wqkv_v], scattered to the
//    dense g_QA / g_KA / g_V arrays (restores fused's proven gather geometry).
// ---------------------------------------------------------------------------
__global__ __launch_bounds__(256)
void xqk_gemm(const float* __restrict__ x, const float* __restrict__ wqkv) {
    __shared__ uint32_t As[2][128][36];
    __shared__ uint32_t Bs[2][32][136];

    const int tid  = threadIdx.x;
    const int lane = tid & 31;
    const int warp = tid >> 5;
    const int wm = (warp >> 2) * 64;
    const int wn = (warp & 3) * 32;
    const int m0 = blockIdx.y * 128;
    const int n0 = blockIdx.x * 128;   // 0,128,...,1024 (never straddles 512/1024)
    const size_t xb  = (size_t)(m0 >> 9) * (D_ * N_);
    const int   nlow = m0 & (N_ - 1);

    float acc[4][4][4];
#pragma unroll
    for (int mi = 0; mi < 4; ++mi)
#pragma unroll
        for (int ni = 0; ni < 4; ++ni)
#pragma unroll
            for (int e = 0; e < 4; ++e) acc[mi][ni][e] = 0.f;

    auto stage = [&](int k0, int buf) {
#pragma unroll
        for (int t = 0; t < 4; ++t) {
            const int idx = tid + t * 256;
            const int r0 = (idx & 31) << 2, c = idx >> 5;
            const float4 v = *(const float4*)(x + xb + (size_t)(k0 + c) * N_ + nlow + r0);
            As[buf][r0 + 0][c] = f2tf32(v.x);
            As[buf][r0 + 1][c] = f2tf32(v.y);
            As[buf][r0 + 2][c] = f2tf32(v.z);
            As[buf][r0 + 3][c] = f2tf32(v.w);
        }
#pragma unroll
        for (int t = 0; t < 4; ++t) {
            const int idx = tid + t * 256;
            const int kr = idx >> 5, nc = (idx & 31) << 2;
            const float* src;
            if (n0 < AH_)            src = g_Wqa + (size_t)(k0 + kr) * AH_ + n0 + nc;
            else if (n0 < 2 * AH_)   src = g_Wqa + (size_t)(D_ + k0 + kr) * AH_ + (n0 - AH_) + nc;
            else                     src = wqkv + (size_t)(k0 + kr) * 384 + 256 + nc;
            const float4 v = *(const float4*)src;
            Bs[buf][kr][nc + 0] = f2tf32(v.x); Bs[buf][kr][nc + 1] = f2tf32(v.y);
            Bs[buf][kr][nc + 2] = f2tf32(v.z); Bs[buf][kr][nc + 3] = f2tf32(v.w);
        }
    };

    auto mmatile = [&](int buf) {
#pragma unroll
        for (int ks = 0; ks < 4; ++ks) {
            const int kk = ks * 8;
            uint32_t af[4][4], bf[4][2];
#pragma unroll
            for (int mi = 0; mi < 4; ++mi) {
                const int rb = wm + mi * 16 + (lane >> 2);
                const int cb = kk + (lane & 3);
                af[mi][0] = As[buf][rb    ][cb    ];
                af[mi][1] = As[buf][rb + 8][cb    ];
                af[mi][2] = As[buf][rb    ][cb + 4];
                af[mi][3] = As[buf][rb + 8][cb + 4];
            }
#pragma unroll
            for (int ni = 0; ni < 4; ++ni) {
                const int nb = wn + ni * 8 + (lane >> 2);
                bf[ni][0] = Bs[buf][kk +     (lane & 3)][nb];
                bf[ni][1] = Bs[buf][kk + 4 + (lane & 3)][nb];
            }
#pragma unroll
            for (int mi = 0; mi < 4; ++mi)
#pragma unroll
                for (int ni = 0; ni < 4; ++ni)
                    mma_tf32(acc[mi][ni], af[mi][0], af[mi][1], af[mi][2], af[mi][3],
                             bf[ni][0], bf[ni][1]);
        }
    };

    stage(0, 0);
    __syncthreads();
#pragma unroll
    for (int t = 0; t < 4; ++t) {
        if (t < 3) stage((t + 1) << 5, (t + 1) & 1);
        mmatile(t & 1);
        __syncthreads();
    }

#pragma unroll
    for (int mi = 0; mi < 4; ++mi) {
        const int r0 = m0 + wm + mi * 16 + (lane >> 2);
#pragma unroll
        for (int ni = 0; ni < 4; ++ni) {
            const int c0 = n0 + wn + ni * 8 + ((lane & 3) << 1);
            float* d0;
            float* d1;
            if (n0 < AH_) {
                d0 = g_QA + (size_t)r0 * AH_ + c0;
                d1 = g_QA + (size_t)(r0 + 8) * AH_ + c0;
            } else if (n0 < 2 * AH_) {
                d0 = g_KA + (size_t)r0 * AH_ + (c0 - AH_);
                d1 = g_KA + (size_t)(r0 + 8) * AH_ + (c0 - AH_);
            } else {
                d0 = g_V + (size_t)r0 * D_ + (c0 - 2 * AH_);
                d1 = g_V + (size_t)(r0 + 8) * D_ + (c0 - 2 * AH_);
            }
            *(float2*)d0 = make_float2(acc[mi][ni][0], acc[mi][ni][1]);
            *(float2*)d1 = make_float2(acc[mi][ni][2], acc[mi][ni][3]);
        }
    }
}

// ---------------------------------------------------------------------------
// 4) MEGA-FUSED (R14-proven pipelined version, R14 gather geometry restored)
// ---------------------------------------------------------------------------
constexpr int SM_HID = 0;
constexpr int SM_BS  = 17408;
constexpr int SM_ASA = 34816;
constexpr int SM_SIM = 68608;
constexpr int SM_QA  = 102400;
constexpr int SM_JJ  = 104512;
constexpr int SM_TOT = 104768;

__global__ __launch_bounds__(256, 2)
void fused_kernel(const float* __restrict__ aw2, float* __restrict__ out) {
    extern __shared__ char smem[];
    uint32_t* sHid = (uint32_t*)(smem + SM_HID);
    uint32_t* sAsA = (uint32_t*)(smem + SM_ASA);
    float*    sPE  = (float*)   (smem + SM_ASA);
    float*    sSIM = (float*)   (smem + SM_SIM);
    float*    sQA  = (float*)   (smem + SM_QA);
    int*      sJJ  = (int*)     (smem + SM_JJ);
    uint32_t* sBuf0 = (uint32_t*)(smem + SM_BS);
    uint32_t* sBuf1 = (uint32_t*)(smem + SM_SIM);

    const int tid  = threadIdx.x;
    const int lane = tid & 31;
    const int warp = tid >> 5;
    const int wm = (warp >> 2) * 32;
    const int wn = (warp & 3) * 32;
    const int m0 = blockIdx.x * 64;
    const int b  = m0 >> 13;
    const int q0 = m0 >> 4;

#pragma unroll
    for (int t = 0; t < 4; ++t) {
        const int idx = tid + t * 256;
        const int r = idx >> 4, c = (idx & 15) << 2;
        const float4 v = *(const float4*)(g_hid + (size_t)(m0 + r) * PH_ + c);
        sHid[r * 68 + c + 0] = f2tf32(v.x); sHid[r * 68 + c + 1] = f2tf32(v.y);
        sHid[r * 68 + c + 2] = f2tf32(v.z); sHid[r * 68 + c + 3] = f2tf32(v.w);
    }
    if (tid < 64) sJJ[tid] = g_idx[m0 + tid];
#pragma unroll
    for (int t = 0; t < 2; ++t) {
        const int u = tid + t * 256;
        const int q = u >> 7, c = u & 127;
        sQA[q * 132 + c] = g_QA[(size_t)(q0 + q) * AH_ + c];
    }
#pragma unroll
    for (int u = 0; u < 4; ++u) {
        const int idx = tid + u * 256;
        const int kr = idx >> 5, nc = (idx & 31) << 2;
        const float4 v = *(const float4*)(g_Wc + (size_t)kr * NC_ + nc);
        sBuf0[kr * 136 + nc + 0] = f2tf32(v.x); sBuf0[kr * 136 + nc + 1] = f2tf32(v.y);
        sBuf0[kr * 136 + nc + 2] = f2tf32(v.z); sBuf0[kr * 136 + nc + 3] = f2tf32(v.w);
    }
    __syncthreads();

    float accA[2][4][4], accS[2][4][4];
#pragma unroll
    for (int mi = 0; mi < 2; ++mi)
#pragma unroll
        for (int ni = 0; ni < 4; ++ni)
#pragma unroll
            for (int e = 0; e < 4; ++e) { accA[mi][ni][e] = 0.f; accS[mi][ni][e] = 0.f; }

    // ================= 26-tile pipeline =================
    for (int i = 0; i < 26; ++i) {
        float4 pf[4];
        const int in = i + 1;
        int chn = 0, sn = 0;
        if (in < 26) {
            if (in < 24) { chn = in / 6; sn = in % 6; }
#pragma unroll
            for (int u = 0; u < 4; ++u) {
                const int idx = tid + u * 256;
                const int kr = idx >> 5, nc = (idx & 31) << 2;
                const float* src;
                if (in >= 24)    src = g_Wc + (size_t)(32 * (in - 24) + kr) * NC_ + AH_ + nc;
                else if (sn < 2) src = g_Wc + (size_t)(32 * sn + kr) * NC_ + chn * 128 + nc;
                else             src = aw2 + (size_t)(chn * 128 + (sn - 2) * 32 + kr) * D_ + nc;
                pf[u] = *(const float4*)src;
            }
        }

        const uint32_t* Bs = (i & 1) ? sBuf1 : sBuf0;
        if (i < 24) {
            const int ch = i / 6, s = i % 6;
            if (s < 2) {
#pragma unroll
                for (int ks = 0; ks < 4; ++ks) {
                    const int kk = ks * 8;
                    uint32_t af[2][4], bf[4][2];
#pragma unroll
                    for (int mi = 0; mi < 2; ++mi) {
                        const int rb = wm + mi * 16 + (lane >> 2);
                        const int cb = 32 * s + kk + (lane & 3);
                        af[mi][0] = sHid[rb * 68 + cb];
                        af[mi][1] = sHid[(rb + 8) * 68 + cb];
                        af[mi][2] = sHid[rb * 68 + cb + 4];
                        af[mi][3] = sHid[(rb + 8) * 68 + cb + 4];
                    }
#pragma unroll
                    for (int ni = 0; ni < 4; ++ni) {
                        const int nb = wn + ni * 8 + (lane >> 2);
                        bf[ni][0] = Bs[(kk +     (lane & 3)) * 136 + nb];
                        bf[ni][1] = Bs[(kk + 4 + (lane & 3)) * 136 + nb];
                    }
#pragma unroll
                    for (int mi = 0; mi < 2; ++mi)
#pragma unroll
                        for (int ni = 0; ni < 4; ++ni)
                            mma_tf32(accA[mi][ni], af[mi][0], af[mi][1], af[mi][2], af[mi][3],
                                     bf[ni][0], bf[ni][1]);
                }
                if (s == 1) {
#pragma unroll
                    for (int mi = 0; mi < 2; ++mi) {
                        const int lr = wm + mi * 16 + (lane >> 2);
                        const int q  = lr >> 4;
                        const int j0 = sJJ[lr], j1 = sJJ[lr + 8];
                        const size_t ka0b = (size_t)(b * N_ + j0) * AH_ + ch * 128;
                        const size_t ka1b = (size_t)(b * N_ + j1) * AH_ + ch * 128;
#pragma unroll
                        for (int ni = 0; ni < 4; ++ni) {
                            const int cl = wn + ni * 8 + ((lane & 3) << 1);
                            const float bc0 = g_bc[ch * 128 + cl], bc1 = g_bc[ch * 128 + cl + 1];
                            const float qa0 = sQA[q * 132 + cl], qa1 = sQA[q * 132 + cl + 1];
                            const float2 ka0 = *(const float2*)(g_KA + ka0b + cl);
                            const float2 ka1 = *(const float2*)(g_KA + ka1b + cl);
                            const float x0 = fmaxf(accA[mi][ni][0] + bc0 + qa0 - ka0.x, 0.f);
                            const float x1 = fmaxf(accA[mi][ni][1] + bc1 + qa1 - ka0.y, 0.f);
                            const float x2 = fmaxf(accA[mi][ni][2] + bc0 + qa0 - ka1.x, 0.f);
                            const float x3 = fmaxf(accA[mi][ni][3] + bc1 + qa1 - ka1.y, 0.f);
                            sAsA[lr * 132 + cl]           = f2tf32(x0);
                            sAsA[lr * 132 + cl + 1]       = f2tf32(x1);
                            sAsA[(lr + 8) * 132 + cl]     = f2tf32(x2);
                            sAsA[(lr + 8) * 132 + cl + 1] = f2tf32(x3);
                            accA[mi][ni][0] = 0.f; accA[mi][ni][1] = 0.f;
                            accA[mi][ni][2] = 0.f; accA[mi][ni][3] = 0.f;
                        }
                    }
                }
            } else {
                const int ts = s - 2;
#pragma unroll
                for (int ks = 0; ks < 4; ++ks) {
                    const int kk = ks * 8;
                    uint32_t af[2][4], bf[4][2];
#pragma unroll
                    for (int mi = 0; mi < 2; ++mi) {
                        const int rb = wm + mi * 16 + (lane >> 2);
                        const int cb = ts * 32 + kk + (lane & 3);
                        af[mi][0] = sAsA[rb * 132 + cb];
                        af[mi][1] = sAsA[(rb + 8) * 132 + cb];
                        af[mi][2] = sAsA[rb * 132 + cb + 4];
                        af[mi][3] = sAsA[(rb + 8) * 132 + cb + 4];
                    }
#pragma unroll
                    for (int ni = 0; ni < 4; ++ni) {
                        const int nb = wn + ni * 8 + (lane >> 2);
                        bf[ni][0] = Bs[(kk +     (lane & 3)) * 136 + nb];
                        bf[ni][1] = Bs[(kk + 4 + (lane & 3)) * 136 + nb];
                    }
#pragma unroll
                    for (int mi = 0; mi < 2; ++mi)
#pragma unroll
                        for (int ni = 0; ni < 4; ++ni)
                            mma_tf32(accS[mi][ni], af[mi][0], af[mi][1], af[mi][2], af[mi][3],
                                     bf[ni][0], bf[ni][1]);
                }
            }
        } else {
            const int t = i - 24;
#pragma unroll
            for (int ks = 0; ks < 4; ++ks) {
                const int kk = ks * 8;
                uint32_t af[2][4], bf[4][2];
#pragma unroll
                for (int mi = 0; mi < 2; ++mi) {
                    const int rb = wm + mi * 16 + (lane >> 2);
                    const int cb = 32 * t + kk + (lane & 3);
                    af[mi][0] = sHid[rb * 68 + cb];
                    af[mi][1] = sHid[(rb + 8) * 68 + cb];
                    af[mi][2] = sHid[rb * 68 + cb + 4];
                    af[mi][3] = sHid[(rb + 8) * 68 + cb + 4];
                }
#pragma unroll
                for (int ni = 0; ni < 4; ++ni) {
                    const int nb = wn + ni * 8 + (lane >> 2);
                    bf[ni][0] = Bs[(kk +     (lane & 3)) * 136 + nb];
                    bf[ni][1] = Bs[(kk + 4 + (lane & 3)) * 136 + nb];
                }
#pragma unroll
                for (int mi = 0; mi < 2; ++mi)
#pragma unroll
                    for (int ni = 0; ni < 4; ++ni)
                        mma_tf32(accA[mi][ni], af[mi][0], af[mi][1], af[mi][2], af[mi][3],
                                 bf[ni][0], bf[ni][1]);
            }
        }

        if (in < 26) {
            uint32_t* Bw = (in & 1) ? sBuf1 : sBuf0;
#pragma unroll
            for (int u = 0; u < 4; ++u) {
                const int idx = tid + u * 256;
                const int kr = idx >> 5, nc = (idx & 31) << 2;
                Bw[kr * 136 + nc + 0] = f2tf32(pf[u].x);
                Bw[kr * 136 + nc + 1] = f2tf32(pf[u].y);
                Bw[kr * 136 + nc + 2] = f2tf32(pf[u].z);
                Bw[kr * 136 + nc + 3] = f2tf32(pf[u].w);
            }
            if (in < 24 && sn == 0 && chn > 0) {
#pragma unroll
                for (int t2 = 0; t2 < 2; ++t2) {
                    const int u2 = tid + t2 * 256;
                    const int q = u2 >> 7, c = u2 & 127;
                    sQA[q * 132 + c] = g_QA[(size_t)(q0 + q) * AH_ + chn * 128 + c];
                }
            }
        }
        __syncthreads();
    }

    // ---- dump SIM + PE (ab2 omitted: constant over softmax axis) ----
#pragma unroll
    for (int mi = 0; mi < 2; ++mi) {
        const int lr = wm + mi * 16 + (lane >> 2);
#pragma unroll
        for (int ni = 0; ni < 4; ++ni) {
            const int cl = wn + ni * 8 + ((lane & 3) << 1);
            sSIM[lr * 132 + cl]           = accS[mi][ni][0];
            sSIM[lr * 132 + cl + 1]       = accS[mi][ni][1];
            sSIM[(lr + 8) * 132 + cl]     = accS[mi][ni][2];
            sSIM[(lr + 8) * 132 + cl + 1] = accS[mi][ni][3];
            sPE[lr * 132 + cl]           = accA[mi][ni][0] + g_bc[AH_ + cl];
            sPE[lr * 132 + cl + 1]       = accA[mi][ni][1] + g_bc[AH_ + cl + 1];
            sPE[(lr + 8) * 132 + cl]     = accA[mi][ni][2] + g_bc[AH_ + cl];
            sPE[(lr + 8) * 132 + cl + 1] = accA[mi][ni][3] + g_bc[AH_ + cl + 1];
        }
    }
    __syncthreads();

    // ---- finalize: softmax over 16 neighbors + v gather, transposed store ----
#pragma unroll
    for (int u = 0; u < 2; ++u) {
        const int item = tid + u * 256;
        const int q = item >> 7, c = item & 127;
        const int r0 = q * 16;
        float mx = -3.4e38f;
#pragma unroll
        for (int kk = 0; kk < K_; ++kk) mx = fmaxf(mx, sSIM[(r0 + kk) * 132 + c]);
        float s = 0.f, agg = 0.f;
#pragma unroll
        for (int kk = 0; kk < K_; ++kk) {
            const float e = expf(sSIM[(r0 + kk) * 132 + c] - mx);
            s += e;
            const int j = sJJ[r0 + kk];
            const float vg = g_V[(size_t)(b * N_ + j) * D_ + c] + sPE[(r0 + kk) * 132 + c];
            agg = fmaf(e, vg, agg);
        }
        const int ig = (q0 + q) & (N_ - 1);
        out[(size_t)b * D_ * N_ + (size_t)c * N_ + ig] = agg / s;
    }
}

// ---------------------------------------------------------------------------
// Launch
// ---------------------------------------------------------------------------
extern "C" void kernel_launch(void* const* d_in, const int* in_sizes, int n_in,
                              void* d_out, int out_size) {
    const float* x    = (const float*)d_in[0];
    const float* pos  = (const float*)d_in[1];
    const float* wqkv = (const float*)d_in[2];
    const float* pw1  = (const float*)d_in[3];
    const float* pb1  = (const float*)d_in[4];
    const float* pw2  = (const float*)d_in[5];
    const float* pb2  = (const float*)d_in[6];
    const float* aw1  = (const float*)d_in[7];
    const float* ab1  = (const float*)d_in[8];
    const float* aw2  = (const float*)d_in[9];
    float* out = (float*)d_out;

    static bool attr_set = false;
    if (!attr_set) {
        cudaFuncSetAttribute(fused_kernel, cudaFuncAttributeMaxDynamicSharedMemorySize, SM_TOT);
        attr_set = true;
    }

    knnhid_prep_kernel<<<128 + 547, 256>>>(pos, pw1, pb1, pw2, pb2, aw1, ab1);
    wqa_gemm<<<dim3(AH_ / 128, 2), 256>>>(wqkv, aw1);
    xqk_gemm<<<dim3(NX / 128, M1 / 128), 256>>>(x, wqkv);
    fused_kernel<<<M2 / 64, 256, SM_TOT>>>(aw2, out);
}

// round 17
// speedup vs baseline: 1.0940x; 1.0810x over previous
#include <cuda_runtime.h>
#include <math.h>
#include <stdint.h>

// ---------------------------------------------------------------------------
// Problem constants
// ---------------------------------------------------------------------------
namespace {
constexpr int B_  = 2;
constexpr int N_  = 512;
constexpr int D_  = 128;
constexpr int PH_ = 64;
constexpr int AH_ = 512;
constexpr int K_  = 16;
constexpr int M1  = B_ * N_;    // 1024
constexpr int M2  = M1 * K_;    // 16384
constexpr int NC_ = AH_ + D_;   // 640
constexpr int NX  = 2 * AH_ + D_;   // 1152
}

// ---------------------------------------------------------------------------
// Scratch (dense per-quantity arrays)
// ---------------------------------------------------------------------------
__device__ int   g_idx[M1 * K_];
__device__ float g_hid[M2 * PH_];
__device__ float g_QA [M1 * AH_];
__device__ float g_KA [M1 * AH_];
__device__ float g_V  [M1 * D_];
__device__ float g_Wqa[2 * D_ * AH_];
__device__ float g_Wc [PH_ * NC_];
__device__ float g_bc [NC_];

__device__ __forceinline__ uint32_t f2tf32(float f) {
    uint32_t u;
    asm("cvt.rna.tf32.f32 %0, %1;" : "=r"(u) : "f"(f));
    return u;
}

__device__ __forceinline__ void mma_tf32(float c[4],
                                         uint32_t a0, uint32_t a1, uint32_t a2, uint32_t a3,
                                         uint32_t b0, uint32_t b1) {
    asm volatile(
        "mma.sync.aligned.m16n8k8.row.col.f32.tf32.tf32.f32 "
        "{%0,%1,%2,%3}, {%4,%5,%6,%7}, {%8,%9}, {%0,%1,%2,%3};"
        : "+f"(c[0]), "+f"(c[1]), "+f"(c[2]), "+f"(c[3])
        : "r"(a0), "r"(a1), "r"(a2), "r"(a3), "r"(b0), "r"(b1));
}

// ---------------------------------------------------------------------------
// 1) knn+hid + prep_w (proven R15/R16)
// ---------------------------------------------------------------------------
__global__ __launch_bounds__(256)
void knnhid_prep_kernel(const float* __restrict__ pos,
                        const float* __restrict__ pw1, const float* __restrict__ pb1,
                        const float* __restrict__ pw2, const float* __restrict__ pb2,
                        const float* __restrict__ aw1, const float* __restrict__ ab1) {
    const int blk = blockIdx.x;
    const int tid = threadIdx.x;

    if (blk >= 128) {
        const int b2 = blk - 128;
        if (b2 < 512) {
            __shared__ float red[4][64];
            const int o = b2 * 64 + (tid & 63);
            const int h = o >> 9, c = o & (AH_ - 1);
            const int sp = tid >> 6;
            float s = 0.f;
#pragma unroll
            for (int u = 0; u < 32; ++u) {
                const int d = sp * 32 + u;
                s = fmaf(pw2[h * D_ + d], aw1[d * AH_ + c], s);
            }
            red[sp][tid & 63] = s;
            __syncthreads();
            if (tid < 64)
                g_Wc[h * NC_ + c] = red[0][tid] + red[1][tid] + red[2][tid] + red[3][tid];
        } else if (b2 < 544) {
            const int u = (b2 - 512) * 256 + tid;
            const int h = u >> 7, d = u & (D_ - 1);
            g_Wc[h * NC_ + AH_ + d] = pw2[h * D_ + d];
        } else {
            const int c = (b2 - 544) * 256 + tid;
            if (c < AH_) {
                float s0 = ab1[c], s1 = 0.f;
#pragma unroll 16
                for (int d = 0; d < D_; d += 2) {
                    s0 = fmaf(pb2[d],     aw1[d * AH_ + c],       s0);
                    s1 = fmaf(pb2[d + 1], aw1[(d + 1) * AH_ + c], s1);
                }
                g_bc[c] = s0 + s1;
            } else if (c < NC_) {
                g_bc[c] = pb2[c - AH_];
            }
        }
        return;
    }

    __shared__ float spx[N_], spy[N_], spz[N_];
    __shared__ int   s_idx[8][K_];

    const int m0 = blk * 8;
    const int b = m0 >> 9;
    const int lane = tid & 31;
    const int warp = tid >> 5;

    for (int t = tid; t < N_; t += 256) {
        const float* p = pos + (size_t)(b * N_ + t) * 3;
        spx[t] = p[0]; spy[t] = p[1]; spz[t] = p[2];
    }
    __syncthreads();

    {
        const int m = m0 + warp;
        const int i = m & (N_ - 1);
        const float px = spx[i], py = spy[i], pz = spz[i];
        float d2[16];
#pragma unroll
        for (int t = 0; t < 16; ++t) {
            const int j = lane + 32 * t;
            const float dx = px - spx[j], dy = py - spy[j], dz = pz - spz[j];
            d2[t] = dx * dx + dy * dy + dz * dz;
        }
        unsigned taken = 0u;
        for (int it = 0; it < K_; ++it) {
            float best = 3.4e38f;
            int bt = -1;
#pragma unroll
            for (int t = 0; t < 16; ++t) {
                if (!((taken >> t) & 1u) && d2[t] < best) { best = d2[t]; bt = t; }
            }
            int bj = (bt < 0) ? 0x7fffffff : (lane + 32 * bt);
#pragma unroll
            for (int off = 16; off; off >>= 1) {
                const float ov = __shfl_xor_sync(0xffffffffu, best, off);
                const int   oj = __shfl_xor_sync(0xffffffffu, bj,   off);
                if (ov < best || (ov == best && oj < bj)) { best = ov; bj = oj; }
            }
            if ((bj & 31) == lane) taken |= 1u << (bj >> 5);
            if (lane == 0) { s_idx[warp][it] = bj; g_idx[m * K_ + it] = bj; }
        }
    }
    __syncthreads();

    const int h = tid & 63;
    const int grp = tid >> 6;
    const float w0 = pw1[h], w1 = pw1[64 + h], w2 = pw1[128 + h], bb = pb1[h];
#pragma unroll
    for (int r = grp * 32; r < grp * 32 + 32; ++r) {
        const int q = r >> 4, kk = r & 15;
        const int iq = (m0 + q) & (N_ - 1);
        const int j = s_idx[q][kk];
        const float rx = spx[iq] - spx[j];
        const float ry = spy[iq] - spy[j];
        const float rz = spz[iq] - spz[j];
        float v = fmaf(rx, w0, fmaf(ry, w1, fmaf(rz, w2, bb)));
        g_hid[(size_t)(m0 * K_ + r) * PH_ + h] = fmaxf(v, 0.f);
    }
}

// ---------------------------------------------------------------------------
// 2) wqa_gemm (proven R15/R16)
// ---------------------------------------------------------------------------
__global__ __launch_bounds__(256)
void wqa_gemm(const float* __restrict__ wqkv, const float* __restrict__ aw1) {
    __shared__ uint32_t As[2][128][36];
    __shared__ uint32_t Bs[2][32][136];

    const int tid  = threadIdx.x;
    const int lane = tid & 31;
    const int warp = tid >> 5;
    const int wm = (warp >> 2) * 64;
    const int wn = (warp & 3) * 32;
    const int m0 = blockIdx.y * 128;
    const int n0 = blockIdx.x * 128;
    const int koff = (m0 >= 128) ? 128 : 0;

    float acc[4][4][4];
#pragma unroll
    for (int mi = 0; mi < 4; ++mi)
#pragma unroll
        for (int ni = 0; ni < 4; ++ni)
#pragma unroll
            for (int e = 0; e < 4; ++e) acc[mi][ni][e] = 0.f;

    auto stage = [&](int k0, int buf) {
#pragma unroll
        for (int t = 0; t < 4; ++t) {
            const int idx = tid + t * 256;
            const int r = idx >> 3, c = (idx & 7) << 2;
            const float4 v = *(const float4*)(wqkv + (size_t)r * 384 + koff + k0 + c);
            As[buf][r][c + 0] = f2tf32(v.x); As[buf][r][c + 1] = f2tf32(v.y);
            As[buf][r][c + 2] = f2tf32(v.z); As[buf][r][c + 3] = f2tf32(v.w);
        }
#pragma unroll
        for (int t = 0; t < 4; ++t) {
            const int idx = tid + t * 256;
            const int kr = idx >> 5, nc = (idx & 31) << 2;
            const float4 v = *(const float4*)(aw1 + (size_t)(k0 + kr) * AH_ + n0 + nc);
            Bs[buf][kr][nc + 0] = f2tf32(v.x); Bs[buf][kr][nc + 1] = f2tf32(v.y);
            Bs[buf][kr][nc + 2] = f2tf32(v.z); Bs[buf][kr][nc + 3] = f2tf32(v.w);
        }
    };

    auto mmatile = [&](int buf) {
#pragma unroll
        for (int ks = 0; ks < 4; ++ks) {
            const int kk = ks * 8;
            uint32_t af[4][4], bf[4][2];
#pragma unroll
            for (int mi = 0; mi < 4; ++mi) {
                const int rb = wm + mi * 16 + (lane >> 2);
                const int cb = kk + (lane & 3);
                af[mi][0] = As[buf][rb    ][cb    ];
                af[mi][1] = As[buf][rb + 8][cb    ];
                af[mi][2] = As[buf][rb    ][cb + 4];
                af[mi][3] = As[buf][rb + 8][cb + 4];
            }
#pragma unroll
            for (int ni = 0; ni < 4; ++ni) {
                const int nb = wn + ni * 8 + (lane >> 2);
                bf[ni][0] = Bs[buf][kk +     (lane & 3)][nb];
                bf[ni][1] = Bs[buf][kk + 4 + (lane & 3)][nb];
            }
#pragma unroll
            for (int mi = 0; mi < 4; ++mi)
#pragma unroll
                for (int ni = 0; ni < 4; ++ni)
                    mma_tf32(acc[mi][ni], af[mi][0], af[mi][1], af[mi][2], af[mi][3],
                             bf[ni][0], bf[ni][1]);
        }
    };

    stage(0, 0);
    __syncthreads();
#pragma unroll
    for (int t = 0; t < 4; ++t) {
        if (t < 3) stage((t + 1) << 5, (t + 1) & 1);
        mmatile(t & 1);
        __syncthreads();
    }

#pragma unroll
    for (int mi = 0; mi < 4; ++mi) {
        const int r0 = m0 + wm + mi * 16 + (lane >> 2);
#pragma unroll
        for (int ni = 0; ni < 4; ++ni) {
            const int c0 = n0 + wn + ni * 8 + ((lane & 3) << 1);
            *(float2*)(g_Wqa + (size_t)r0 * AH_ + c0)       = make_float2(acc[mi][ni][0], acc[mi][ni][1]);
            *(float2*)(g_Wqa + (size_t)(r0 + 8) * AH_ + c0) = make_float2(acc[mi][ni][2], acc[mi][ni][3]);
        }
    }
}

// ---------------------------------------------------------------------------
// 3) xqk_gemm -> dense g_QA / g_KA / g_V (proven R16)
// ---------------------------------------------------------------------------
__global__ __launch_bounds__(256)
void xqk_gemm(const float* __restrict__ x, const float* __restrict__ wqkv) {
    __shared__ uint32_t As[2][128][36];
    __shared__ uint32_t Bs[2][32][136];

    const int tid  = threadIdx.x;
    const int lane = tid & 31;
    const int warp = tid >> 5;
    const int wm = (warp >> 2) * 64;
    const int wn = (warp & 3) * 32;
    const int m0 = blockIdx.y * 128;
    const int n0 = blockIdx.x * 128;
    const size_t xb  = (size_t)(m0 >> 9) * (D_ * N_);
    const int   nlow = m0 & (N_ - 1);

    float acc[4][4][4];
#pragma unroll
    for (int mi = 0; mi < 4; ++mi)
#pragma unroll
        for (int ni = 0; ni < 4; ++ni)
#pragma unroll
            for (int e = 0; e < 4; ++e) acc[mi][ni][e] = 0.f;

    auto stage = [&](int k0, int buf) {
#pragma unroll
        for (int t = 0; t < 4; ++t) {
            const int idx = tid + t * 256;
            const int r0 = (idx & 31) << 2, c = idx >> 5;
            const float4 v = *(const float4*)(x + xb + (size_t)(k0 + c) * N_ + nlow + r0);
            As[buf][r0 + 0][c] = f2tf32(v.x);
            As[buf][r0 + 1][c] = f2tf32(v.y);
            As[buf][r0 + 2][c] = f2tf32(v.z);
            As[buf][r0 + 3][c] = f2tf32(v.w);
        }
#pragma unroll
        for (int t = 0; t < 4; ++t) {
            const int idx = tid + t * 256;
            const int kr = idx >> 5, nc = (idx & 31) << 2;
            const float* src;
            if (n0 < AH_)            src = g_Wqa + (size_t)(k0 + kr) * AH_ + n0 + nc;
            else if (n0 < 2 * AH_)   src = g_Wqa + (size_t)(D_ + k0 + kr) * AH_ + (n0 - AH_) + nc;
            else                     src = wqkv + (size_t)(k0 + kr) * 384 + 256 + nc;
            const float4 v = *(const float4*)src;
            Bs[buf][kr][nc + 0] = f2tf32(v.x); Bs[buf][kr][nc + 1] = f2tf32(v.y);
            Bs[buf][kr][nc + 2] = f2tf32(v.z); Bs[buf][kr][nc + 3] = f2tf32(v.w);
        }
    };

    auto mmatile = [&](int buf) {
#pragma unroll
        for (int ks = 0; ks < 4; ++ks) {
            const int kk = ks * 8;
            uint32_t af[4][4], bf[4][2];
#pragma unroll
            for (int mi = 0; mi < 4; ++mi) {
                const int rb = wm + mi * 16 + (lane >> 2);
                const int cb = kk + (lane & 3);
                af[mi][0] = As[buf][rb    ][cb    ];
                af[mi][1] = As[buf][rb + 8][cb    ];
                af[mi][2] = As[buf][rb    ][cb + 4];
                af[mi][3] = As[buf][rb + 8][cb + 4];
            }
#pragma unroll
            for (int ni = 0; ni < 4; ++ni) {
                const int nb = wn + ni * 8 + (lane >> 2);
                bf[ni][0] = Bs[buf][kk +     (lane & 3)][nb];
                bf[ni][1] = Bs[buf][kk + 4 + (lane & 3)][nb];
            }
#pragma unroll
            for (int mi = 0; mi < 4; ++mi)
#pragma unroll
                for (int ni = 0; ni < 4; ++ni)
                    mma_tf32(acc[mi][ni], af[mi][0], af[mi][1], af[mi][2], af[mi][3],
                             bf[ni][0], bf[ni][1]);
        }
    };

    stage(0, 0);
    __syncthreads();
#pragma unroll
    for (int t = 0; t < 4; ++t) {
        if (t < 3) stage((t + 1) << 5, (t + 1) & 1);
        mmatile(t & 1);
        __syncthreads();
    }

#pragma unroll
    for (int mi = 0; mi < 4; ++mi) {
        const int r0 = m0 + wm + mi * 16 + (lane >> 2);
#pragma unroll
        for (int ni = 0; ni < 4; ++ni) {
            const int c0 = n0 + wn + ni * 8 + ((lane & 3) << 1);
            float* d0;
            float* d1;
            if (n0 < AH_) {
                d0 = g_QA + (size_t)r0 * AH_ + c0;
                d1 = g_QA + (size_t)(r0 + 8) * AH_ + c0;
            } else if (n0 < 2 * AH_) {
                d0 = g_KA + (size_t)r0 * AH_ + (c0 - AH_);
                d1 = g_KA + (size_t)(r0 + 8) * AH_ + (c0 - AH_);
            } else {
                d0 = g_V + (size_t)r0 * D_ + (c0 - 2 * AH_);
                d1 = g_V + (size_t)(r0 + 8) * D_ + (c0 - 2 * AH_);
            }
            *(float2*)d0 = make_float2(acc[mi][ni][0], acc[mi][ni][1]);
            *(float2*)d1 = make_float2(acc[mi][ni][2], acc[mi][ni][3]);
        }
    }
}

// ---------------------------------------------------------------------------
// 4) MEGA-FUSED — R13's un-pipelined variant (measured 47us/78 total),
//    restored verbatim; only QA/KA/V addressing switched to dense arrays.
// ---------------------------------------------------------------------------
constexpr int SM_HID = 0;
constexpr int SM_BS  = 17408;
constexpr int SM_ASA = 34816;
constexpr int SM_SIM = 68608;
constexpr int SM_QA  = 102400;
constexpr int SM_JJ  = 104512;
constexpr int SM_TOT = 104768;

__global__ __launch_bounds__(256)
void fused_kernel(const float* __restrict__ aw2, float* __restrict__ out) {
    extern __shared__ char smem[];
    uint32_t* sHid = (uint32_t*)(smem + SM_HID);
    uint32_t* sBs  = (uint32_t*)(smem + SM_BS);
    uint32_t* sAsA = (uint32_t*)(smem + SM_ASA);
    float*    sPE  = (float*)   (smem + SM_ASA);
    float*    sSIM = (float*)   (smem + SM_SIM);
    float*    sQA  = (float*)   (smem + SM_QA);
    int*      sJJ  = (int*)     (smem + SM_JJ);

    const int tid  = threadIdx.x;
    const int lane = tid & 31;
    const int warp = tid >> 5;
    const int wm = (warp >> 2) * 32;
    const int wn = (warp & 3) * 32;
    const int m0 = blockIdx.x * 64;
    const int b  = m0 >> 13;
    const int q0 = m0 >> 4;

    // ---- stage hid (64x64 tf32) + neighbor indices ----
#pragma unroll
    for (int t = 0; t < 4; ++t) {
        const int idx = tid + t * 256;
        const int r = idx >> 4, c = (idx & 15) << 2;
        const float4 v = *(const float4*)(g_hid + (size_t)(m0 + r) * PH_ + c);
        sHid[r * 68 + c + 0] = f2tf32(v.x); sHid[r * 68 + c + 1] = f2tf32(v.y);
        sHid[r * 68 + c + 2] = f2tf32(v.z); sHid[r * 68 + c + 3] = f2tf32(v.w);
    }
    if (tid < 64) sJJ[tid] = g_idx[m0 + tid];
    __syncthreads();

    float accS[2][4][4];
#pragma unroll
    for (int mi = 0; mi < 2; ++mi)
#pragma unroll
        for (int ni = 0; ni < 4; ++ni)
#pragma unroll
            for (int e = 0; e < 4; ++e) accS[mi][ni][e] = 0.f;

    // ================= chunks over AH =================
    for (int ch = 0; ch < 4; ++ch) {
        const int n0c = ch * 128;

        // QA for these 4 queries, this chunk
#pragma unroll
        for (int t = 0; t < 2; ++t) {
            const int u = tid + t * 256;
            const int q = u >> 7, c = u & 127;
            sQA[q * 132 + c] = g_QA[(size_t)(q0 + q) * AH_ + n0c + c];
        }

        float accA[2][4][4];
#pragma unroll
        for (int mi = 0; mi < 2; ++mi)
#pragma unroll
            for (int ni = 0; ni < 4; ++ni)
#pragma unroll
                for (int e = 0; e < 4; ++e) accA[mi][ni][e] = 0.f;

        // ---- Ablk = hid @ Wc[:, n0c..n0c+128) ----
#pragma unroll
        for (int t = 0; t < 2; ++t) {
            __syncthreads();
#pragma unroll
            for (int u = 0; u < 4; ++u) {
                const int idx = tid + u * 256;
                const int kr = idx >> 5, nc = (idx & 31) << 2;
                const float4 v = *(const float4*)(g_Wc + (size_t)(32 * t + kr) * NC_ + n0c + nc);
                sBs[kr * 136 + nc + 0] = f2tf32(v.x); sBs[kr * 136 + nc + 1] = f2tf32(v.y);
                sBs[kr * 136 + nc + 2] = f2tf32(v.z); sBs[kr * 136 + nc + 3] = f2tf32(v.w);
            }
            __syncthreads();
#pragma unroll
            for (int ks = 0; ks < 4; ++ks) {
                const int kk = ks * 8;
                uint32_t af[2][4], bf[4][2];
#pragma unroll
                for (int mi = 0; mi < 2; ++mi) {
                    const int rb = wm + mi * 16 + (lane >> 2);
                    const int cb = 32 * t + kk + (lane & 3);
                    af[mi][0] = sHid[rb * 68 + cb];
                    af[mi][1] = sHid[(rb + 8) * 68 + cb];
                    af[mi][2] = sHid[rb * 68 + cb + 4];
                    af[mi][3] = sHid[(rb + 8) * 68 + cb + 4];
                }
#pragma unroll
                for (int ni = 0; ni < 4; ++ni) {
                    const int nb = wn + ni * 8 + (lane >> 2);
                    bf[ni][0] = sBs[(kk +     (lane & 3)) * 136 + nb];
                    bf[ni][1] = sBs[(kk + 4 + (lane & 3)) * 136 + nb];
                }
#pragma unroll
                for (int mi = 0; mi < 2; ++mi)
#pragma unroll
                    for (int ni = 0; ni < 4; ++ni)
                        mma_tf32(accA[mi][ni], af[mi][0], af[mi][1], af[mi][2], af[mi][3],
                                 bf[ni][0], bf[ni][1]);
            }
        }
        __syncthreads();   // prior chunk's SIM mma done reading sAsA

        // ---- epilogue: + bc + QA - KA, relu -> sAsA (tf32) ----
#pragma unroll
        for (int mi = 0; mi < 2; ++mi) {
            const int lr = wm + mi * 16 + (lane >> 2);
            const int q  = lr >> 4;
            const int j0 = sJJ[lr], j1 = sJJ[lr + 8];
            const size_t ka0b = (size_t)(b * N_ + j0) * AH_ + n0c;
            const size_t ka1b = (size_t)(b * N_ + j1) * AH_ + n0c;
#pragma unroll
            for (int ni = 0; ni < 4; ++ni) {
                const int cl = wn + ni * 8 + ((lane & 3) << 1);
                const float bc0 = g_bc[n0c + cl], bc1 = g_bc[n0c + cl + 1];
                const float qa0 = sQA[q * 132 + cl], qa1 = sQA[q * 132 + cl + 1];
                const float2 ka0 = *(const float2*)(g_KA + ka0b + cl);
                const float2 ka1 = *(const float2*)(g_KA + ka1b + cl);
                const float x0 = fmaxf(accA[mi][ni][0] + bc0 + qa0 - ka0.x, 0.f);
                const float x1 = fmaxf(accA[mi][ni][1] + bc1 + qa1 - ka0.y, 0.f);
                const float x2 = fmaxf(accA[mi][ni][2] + bc0 + qa0 - ka1.x, 0.f);
                const float x3 = fmaxf(accA[mi][ni][3] + bc1 + qa1 - ka1.y, 0.f);
                sAsA[lr * 132 + cl]           = f2tf32(x0);
                sAsA[lr * 132 + cl + 1]       = f2tf32(x1);
                sAsA[(lr + 8) * 132 + cl]     = f2tf32(x2);
                sAsA[(lr + 8) * 132 + cl + 1] = f2tf32(x3);
            }
        }

        // ---- SIM += Ablk @ aw2[n0c..n0c+128, :] ----
#pragma unroll
        for (int ts = 0; ts < 4; ++ts) {
            __syncthreads();
#pragma unroll
            for (int u = 0; u < 4; ++u) {
                const int idx = tid + u * 256;
                const int kr = idx >> 5, nc = (idx & 31) << 2;
                const float4 v = *(const float4*)(aw2 + (size_t)(n0c + ts * 32 + kr) * D_ + nc);
                sBs[kr * 136 + nc + 0] = f2tf32(v.x); sBs[kr * 136 + nc + 1] = f2tf32(v.y);
                sBs[kr * 136 + nc + 2] = f2tf32(v.z); sBs[kr * 136 + nc + 3] = f2tf32(v.w);
            }
            __syncthreads();
#pragma unroll
            for (int ks = 0; ks < 4; ++ks) {
                const int kk = ks * 8;
                uint32_t af[2][4], bf[4][2];
#pragma unroll
                for (int mi = 0; mi < 2; ++mi) {
                    const int rb = wm + mi * 16 + (lane >> 2);
                    const int cb = ts * 32 + kk + (lane & 3);
                    af[mi][0] = sAsA[rb * 132 + cb];
                    af[mi][1] = sAsA[(rb + 8) * 132 + cb];
                    af[mi][2] = sAsA[rb * 132 + cb + 4];
                    af[mi][3] = sAsA[(rb + 8) * 132 + cb + 4];
                }
#pragma unroll
                for (int ni = 0; ni < 4; ++ni) {
                    const int nb = wn + ni * 8 + (lane >> 2);
                    bf[ni][0] = sBs[(kk +     (lane & 3)) * 136 + nb];
                    bf[ni][1] = sBs[(kk + 4 + (lane & 3)) * 136 + nb];
                }
#pragma unroll
                for (int mi = 0; mi < 2; ++mi)
#pragma unroll
                    for (int ni = 0; ni < 4; ++ni)
                        mma_tf32(accS[mi][ni], af[mi][0], af[mi][1], af[mi][2], af[mi][3],
                                 bf[ni][0], bf[ni][1]);
            }
        }
    }

    // ---- dump SIM (ab2 omitted: constant over softmax axis) ----
#pragma unroll
    for (int mi = 0; mi < 2; ++mi) {
        const int lr = wm + mi * 16 + (lane >> 2);
#pragma unroll
        for (int ni = 0; ni < 4; ++ni) {
            const int cl = wn + ni * 8 + ((lane & 3) << 1);
            sSIM[lr * 132 + cl]           = accS[mi][ni][0];
            sSIM[lr * 132 + cl + 1]       = accS[mi][ni][1];
            sSIM[(lr + 8) * 132 + cl]     = accS[mi][ni][2];
            sSIM[(lr + 8) * 132 + cl + 1] = accS[mi][ni][3];
        }
    }
    __syncthreads();

    // ---- PE = hid @ Wc[:,512:640) + bc -> sPE (reuses sAsA region) ----
    {
        float accP[2][4][4];
#pragma unroll
        for (int mi = 0; mi < 2; ++mi)
#pragma unroll
            for (int ni = 0; ni < 4; ++ni)
#pragma unroll
                for (int e = 0; e < 4; ++e) accP[mi][ni][e] = 0.f;
#pragma unroll
        for (int t = 0; t < 2; ++t) {
            __syncthreads();
#pragma unroll
            for (int u = 0; u < 4; ++u) {
                const int idx = tid + u * 256;
                const int kr = idx >> 5, nc = (idx & 31) << 2;
                const float4 v = *(const float4*)(g_Wc + (size_t)(32 * t + kr) * NC_ + AH_ + nc);
                sBs[kr * 136 + nc + 0] = f2tf32(v.x); sBs[kr * 136 + nc + 1] = f2tf32(v.y);
                sBs[kr * 136 + nc + 2] = f2tf32(v.z); sBs[kr * 136 + nc + 3] = f2tf32(v.w);
            }
            __syncthreads();
#pragma unroll
            for (int ks = 0; ks < 4; ++ks) {
                const int kk = ks * 8;
                uint32_t af[2][4], bf[4][2];
#pragma unroll
                for (int mi = 0; mi < 2; ++mi) {
                    const int rb = wm + mi * 16 + (lane >> 2);
                    const int cb = 32 * t + kk + (lane & 3);
                    af[mi][0] = sHid[rb * 68 + cb];
                    af[mi][1] = sHid[(rb + 8) * 68 + cb];
                    af[mi][2] = sHid[rb * 68 + cb + 4];
                    af[mi][3] = sHid[(rb + 8) * 68 + cb + 4];
                }
#pragma unroll
                for (int ni = 0; ni < 4; ++ni) {
                    const int nb = wn + ni * 8 + (lane >> 2);
                    bf[ni][0] = sBs[(kk +     (lane & 3)) * 136 + nb];
                    bf[ni][1] = sBs[(kk + 4 + (lane & 3)) * 136 + nb];
                }
#pragma unroll
                for (int mi = 0; mi < 2; ++mi)
#pragma unroll
                    for (int ni = 0; ni < 4; ++ni)
                        mma_tf32(accP[mi][ni], af[mi][0], af[mi][1], af[mi][2], af[mi][3],
                                 bf[ni][0], bf[ni][1]);
            }
        }
        __syncthreads();
#pragma unroll
        for (int mi = 0; mi < 2; ++mi) {
            const int lr = wm + mi * 16 + (lane >> 2);
#pragma unroll
            for (int ni = 0; ni < 4; ++ni) {
                const int cl = wn + ni * 8 + ((lane & 3) << 1);
                sPE[lr * 132 + cl]           = accP[mi][ni][0] + g_bc[AH_ + cl];
                sPE[lr * 132 + cl + 1]       = accP[mi][ni][1] + g_bc[AH_ + cl + 1];
                sPE[(lr + 8) * 132 + cl]     = accP[mi][ni][2] + g_bc[AH_ + cl];
                sPE[(lr + 8) * 132 + cl + 1] = accP[mi][ni][3] + g_bc[AH_ + cl + 1];
            }
        }
    }
    __syncthreads();

    // ---- finalize: softmax over 16 neighbors + v gather, transposed store ----
#pragma unroll
    for (int u = 0; u < 2; ++u) {
        const int item = tid + u * 256;
        const int q = item >> 7, c = item & 127;
        const int r0 = q * 16;
        float mx = -3.4e38f;
#pragma unroll
        for (int kk = 0; kk < K_; ++kk) mx = fmaxf(mx, sSIM[(r0 + kk) * 132 + c]);
        float s = 0.f, agg = 0.f;
#pragma unroll
        for (int kk = 0; kk < K_; ++kk) {
            const float e = expf(sSIM[(r0 + kk) * 132 + c] - mx);
            s += e;
            const int j = sJJ[r0 + kk];
            const float vg = g_V[(size_t)(b * N_ + j) * D_ + c] + sPE[(r0 + kk) * 132 + c];
            agg = fmaf(e, vg, agg);
        }
        const int ig = (q0 + q) & (N_ - 1);
        out[(size_t)b * D_ * N_ + (size_t)c * N_ + ig] = agg / s;
    }
}

// ---------------------------------------------------------------------------
// Launch
// ---------------------------------------------------------------------------
extern "C" void kernel_launch(void* const* d_in, const int* in_sizes, int n_in,
                              void* d_out, int out_size) {
    const float* x    = (const float*)d_in[0];
    const float* pos  = (const float*)d_in[1];
    const float* wqkv = (const float*)d_in[2];
    const float* pw1  = (const float*)d_in[3];
    const float* pb1  = (const float*)d_in[4];
    const float* pw2  = (const float*)d_in[5];
    const float* pb2  = (const float*)d_in[6];
    const float* aw1  = (const float*)d_in[7];
    const float* ab1  = (const float*)d_in[8];
    const float* aw2  = (const float*)d_in[9];
    float* out = (float*)d_out;

    static bool attr_set = false;
    if (!attr_set) {
        cudaFuncSetAttribute(fused_kernel, cudaFuncAttributeMaxDynamicSharedMemorySize, SM_TOT);
        attr_set = true;
    }

    knnhid_prep_kernel<<<128 + 547, 256>>>(pos, pw1, pb1, pw2, pb2, aw1, ab1);
    wqa_gemm<<<dim3(AH_ / 128, 2), 256>>>(wqkv, aw1);
    xqk_gemm<<<dim3(NX / 128, M1 / 128), 256>>>(x, wqkv);
    fused_kernel<<<M2 / 64, 256, SM_TOT>>>(aw2, out);
}